// round 1
// baseline (speedup 1.0000x reference)
#include <cuda_runtime.h>
#include <cuda_bf16.h>

// Problem shape (fixed by setup_inputs): B=1, H=8, N=4096, D=64, fp32.
#define HEADS 8
#define NSEQ  4096
#define DDIM  64
#define TILE  128
#define SPAD  68            // smem row stride in floats (16B aligned, conflict-managed)

// Scratch for row norms (allocation-free per harness rules).
__device__ float g_q2[HEADS * NSEQ];
__device__ float g_k2[HEADS * NSEQ];

// ---------------------------------------------------------------------------
// Kernel 1: per-row squared norms for Q and K. 32768 rows per tensor, 64 floats
// each; one thread per row, float4 loads. Trivially fast (~8 MB read).
// ---------------------------------------------------------------------------
__global__ void hept_norms_kernel(const float* __restrict__ q,
                                  const float* __restrict__ k) {
    int row = blockIdx.x * blockDim.x + threadIdx.x;      // 0 .. HEADS*NSEQ-1
    if (row >= HEADS * NSEQ) return;
    const float* src = (blockIdx.y == 0) ? q : k;
    float*       dst = (blockIdx.y == 0) ? g_q2 : g_k2;
    const float4* p = reinterpret_cast<const float4*>(src + (size_t)row * DDIM);
    float s = 0.f;
#pragma unroll
    for (int i = 0; i < DDIM / 4; ++i) {
        float4 v = p[i];
        s += v.x * v.x + v.y * v.y + v.z * v.z + v.w * v.w;
    }
    dst[row] = s;
}

// ---------------------------------------------------------------------------
// Kernel 2: main fused GEMM + exp epilogue.
// Grid: (N/TILE, N/TILE, HEADS). Block: 256 threads.
// Each CTA computes a 128x128 tile of out[h] = exp(-0.5*(q2 + k2 - 2 Q K^T)).
// Each thread: 8x8 micro-tile, rows = ty*8+i (contiguous), cols = tx + 16*j
// (strided, so vector LDS over kk is bank-conflict-free and the scalar store
// pattern is sector-perfect: 16 lanes x 4B contiguous per j).
// ---------------------------------------------------------------------------
__global__ __launch_bounds__(256)
void hept_main_kernel(const float* __restrict__ Q,
                      const float* __restrict__ K,
                      float* __restrict__ out) {
    __shared__ float Qs[TILE * SPAD];
    __shared__ float Ks[TILE * SPAD];

    const int h    = blockIdx.z;
    const int row0 = blockIdx.y * TILE;
    const int col0 = blockIdx.x * TILE;

    const float* Qh = Q + (size_t)h * NSEQ * DDIM;
    const float* Kh = K + (size_t)h * NSEQ * DDIM;

    const int tid = threadIdx.x;
    const int tx  = tid & 15;          // 0..15 -> column group
    const int ty  = tid >> 4;          // 0..15 -> row group

    // --- cooperative load: 128 rows x 64 floats per tile = 2048 float4 each.
    // thread t handles float4 indices t, t+256, ... (8 iterations per tile).
    // global: fully coalesced (consecutive lanes -> consecutive 16B chunks of a row).
#pragma unroll
    for (int it = 0; it < 8; ++it) {
        int idx = tid + it * 256;      // 0..2047
        int r   = idx >> 4;            // row within tile
        int c4  = idx & 15;            // which float4 along D
        float4 vq = reinterpret_cast<const float4*>(Qh + (size_t)(row0 + r) * DDIM)[c4];
        float4 vk = reinterpret_cast<const float4*>(Kh + (size_t)(col0 + r) * DDIM)[c4];
        reinterpret_cast<float4*>(&Qs[r * SPAD + c4 * 4])[0] = vq;
        reinterpret_cast<float4*>(&Ks[r * SPAD + c4 * 4])[0] = vk;
    }
    __syncthreads();

    float acc[8][8];
#pragma unroll
    for (int i = 0; i < 8; ++i)
#pragma unroll
        for (int j = 0; j < 8; ++j) acc[i][j] = 0.f;

    // --- main loop over D in steps of 4 (float4 vector LDS).
#pragma unroll
    for (int kk = 0; kk < DDIM; kk += 4) {
        float4 a[8], b[8];
#pragma unroll
        for (int i = 0; i < 8; ++i)
            a[i] = *reinterpret_cast<const float4*>(&Qs[(ty * 8 + i) * SPAD + kk]);
#pragma unroll
        for (int j = 0; j < 8; ++j)
            b[j] = *reinterpret_cast<const float4*>(&Ks[(tx + 16 * j) * SPAD + kk]);
#pragma unroll
        for (int i = 0; i < 8; ++i) {
#pragma unroll
            for (int j = 0; j < 8; ++j) {
                acc[i][j] = fmaf(a[i].x, b[j].x, acc[i][j]);
                acc[i][j] = fmaf(a[i].y, b[j].y, acc[i][j]);
                acc[i][j] = fmaf(a[i].z, b[j].z, acc[i][j]);
                acc[i][j] = fmaf(a[i].w, b[j].w, acc[i][j]);
            }
        }
    }

    // --- epilogue: dist^2 = q2 + k2 - 2*qk, clamp, exp(-0.5 * dist^2)
    float q2r[8], k2c[8];
#pragma unroll
    for (int i = 0; i < 8; ++i)
        q2r[i] = g_q2[h * NSEQ + row0 + ty * 8 + i];
#pragma unroll
    for (int j = 0; j < 8; ++j)
        k2c[j] = g_k2[h * NSEQ + col0 + tx + 16 * j];

    float* outh = out + (size_t)h * NSEQ * NSEQ;
#pragma unroll
    for (int i = 0; i < 8; ++i) {
        const int row = row0 + ty * 8 + i;
        float* orow = outh + (size_t)row * NSEQ + col0;
#pragma unroll
        for (int j = 0; j < 8; ++j) {
            float d = fmaf(-2.f, acc[i][j], q2r[i] + k2c[j]);
            d = fmaxf(d, 0.f);
            orow[tx + 16 * j] = __expf(-0.5f * d);
        }
    }
}

// ---------------------------------------------------------------------------
extern "C" void kernel_launch(void* const* d_in, const int* in_sizes, int n_in,
                              void* d_out, int out_size) {
    const float* q = (const float*)d_in[0];
    const float* k = (const float*)d_in[1];
    float* out = (float*)d_out;

    // norms: HEADS*NSEQ rows per tensor, 256 threads/block, y selects q/k.
    dim3 ngrid((HEADS * NSEQ + 255) / 256, 2, 1);
    hept_norms_kernel<<<ngrid, 256>>>(q, k);

    dim3 mgrid(NSEQ / TILE, NSEQ / TILE, HEADS);
    hept_main_kernel<<<mgrid, 256>>>(q, k, out);
}

// round 3
// speedup vs baseline: 3.5112x; 3.5112x over previous
#include <cuda_runtime.h>
#include <cuda_fp16.h>
#include <cstdint>

// Shape fixed by setup_inputs: B=1, H=8, N=4096, D=64, fp32 in/out.
#define HEADS 8
#define NSEQ  4096
#define DDIM  64
#define TILE  128

// SW128 swizzle (Swizzle<3,4,3>) on byte offsets relative to a 1024B-aligned base.
#define SW128(off) ((off) ^ ((((uint32_t)(off)) >> 3) & 0x70))

__device__ float g_q2[HEADS * NSEQ];
__device__ float g_k2[HEADS * NSEQ];

// ---------------------------------------------------------------------------
// Kernel 1: per-row squared norms (fp32 exact).
// ---------------------------------------------------------------------------
__global__ void hept_norms_kernel(const float* __restrict__ q,
                                  const float* __restrict__ k) {
    int row = blockIdx.x * blockDim.x + threadIdx.x;
    if (row >= HEADS * NSEQ) return;
    const float* src = (blockIdx.y == 0) ? q : k;
    float*       dst = (blockIdx.y == 0) ? g_q2 : g_k2;
    const float4* p = reinterpret_cast<const float4*>(src + (size_t)row * DDIM);
    float s = 0.f;
#pragma unroll
    for (int i = 0; i < DDIM / 4; ++i) {
        float4 v = p[i];
        s += v.x * v.x + v.y * v.y + v.z * v.z + v.w * v.w;
    }
    dst[row] = s;
}

// ---------------------------------------------------------------------------
static __device__ __forceinline__ uint32_t smem_u32(const void* p) {
    uint32_t a;
    asm("{ .reg .u64 t; cvta.to.shared.u64 t, %1; cvt.u32.u64 %0, t; }"
        : "=r"(a) : "l"(p));
    return a;
}

#define LDMATRIX_X4(r0, r1, r2, r3, addr)                                     \
    asm volatile("ldmatrix.sync.aligned.m8n8.x4.shared.b16 {%0,%1,%2,%3}, [%4];" \
                 : "=r"(r0), "=r"(r1), "=r"(r2), "=r"(r3) : "r"(addr))

#define MMA_16816(c, a, b)                                                     \
    asm volatile("mma.sync.aligned.m16n8k16.row.col.f32.f16.f16.f32 "         \
                 "{%0,%1,%2,%3}, {%4,%5,%6,%7}, {%8,%9}, {%0,%1,%2,%3};"      \
                 : "+f"((c)[0]), "+f"((c)[1]), "+f"((c)[2]), "+f"((c)[3])     \
                 : "r"((a)[0]), "r"((a)[1]), "r"((a)[2]), "r"((a)[3]),        \
                   "r"((b)[0]), "r"((b)[1]))

// ---------------------------------------------------------------------------
// Kernel 2: HMMA fp16-split GEMM + exp epilogue.
// Grid (32, 32, 8), 256 threads (8 warps, 2m x 4n), warp tile 64x32.
// dyn smem (1024-aligned): Qhi | Qlo | Khi | Klo, each 128x64 fp16 = 16KB.
// ---------------------------------------------------------------------------
#define SM_TILEB 16384
#define SM_ALLOC (4 * SM_TILEB + 1024)

__global__ __launch_bounds__(256, 2)
void hept_mma_kernel(const float* __restrict__ Q,
                     const float* __restrict__ K,
                     float* __restrict__ out) {
    extern __shared__ char smem_raw[];
    const uint32_t sbase = smem_u32(smem_raw);
    const uint32_t abase = (sbase + 1023u) & ~1023u;
    char* base = smem_raw + (abase - sbase);

    const uint32_t QHI = abase;
    const uint32_t QLO = abase + SM_TILEB;
    const uint32_t KHI = abase + 2 * SM_TILEB;
    const uint32_t KLO = abase + 3 * SM_TILEB;
    char* qhi = base;
    char* qlo = base + SM_TILEB;
    char* khi = base + 2 * SM_TILEB;
    char* klo = base + 3 * SM_TILEB;

    const int tid  = threadIdx.x;
    const int lane = tid & 31;
    const int wid  = tid >> 5;
    const int wm   = wid >> 2;          // 0..1 -> 64-row slab
    const int wn   = wid & 3;           // 0..3 -> 32-col slab
    const int h    = blockIdx.z;
    const int row0 = blockIdx.y * TILE;
    const int col0 = blockIdx.x * TILE;

    const float* Qh = Q + (size_t)h * NSEQ * DDIM;
    const float* Kh = K + (size_t)h * NSEQ * DDIM;

    // --- load fp32 tiles, split fp16 hi/lo, store swizzled.
    // 2048 float4 per tensor / 256 threads = 8 iters (Q and K together).
#pragma unroll
    for (int it = 0; it < 8; ++it) {
        int idx = tid + it * 256;
        int r  = idx >> 4;              // row in tile
        int c4 = idx & 15;              // float4 index along D
        uint32_t off = SW128((uint32_t)(r * 128 + c4 * 8));

        float4 v = reinterpret_cast<const float4*>(Qh + (size_t)(row0 + r) * DDIM)[c4];
        __half2 h01 = __floats2half2_rn(v.x, v.y);
        __half2 h23 = __floats2half2_rn(v.z, v.w);
        float2 f01 = __half22float2(h01);
        float2 f23 = __half22float2(h23);
        __half2 l01 = __floats2half2_rn(v.x - f01.x, v.y - f01.y);
        __half2 l23 = __floats2half2_rn(v.z - f23.x, v.w - f23.y);
        *reinterpret_cast<uint2*>(qhi + off) =
            make_uint2(*reinterpret_cast<uint32_t*>(&h01), *reinterpret_cast<uint32_t*>(&h23));
        *reinterpret_cast<uint2*>(qlo + off) =
            make_uint2(*reinterpret_cast<uint32_t*>(&l01), *reinterpret_cast<uint32_t*>(&l23));

        float4 w = reinterpret_cast<const float4*>(Kh + (size_t)(col0 + r) * DDIM)[c4];
        __half2 g01 = __floats2half2_rn(w.x, w.y);
        __half2 g23 = __floats2half2_rn(w.z, w.w);
        float2 e01 = __half22float2(g01);
        float2 e23 = __half22float2(g23);
        __half2 m01 = __floats2half2_rn(w.x - e01.x, w.y - e01.y);
        __half2 m23 = __floats2half2_rn(w.z - e23.x, w.w - e23.y);
        *reinterpret_cast<uint2*>(khi + off) =
            make_uint2(*reinterpret_cast<uint32_t*>(&g01), *reinterpret_cast<uint32_t*>(&g23));
        *reinterpret_cast<uint2*>(klo + off) =
            make_uint2(*reinterpret_cast<uint32_t*>(&m01), *reinterpret_cast<uint32_t*>(&m23));
    }
    __syncthreads();

    // --- lane-invariant ldmatrix address pieces.
    // A (16x16 tile): lanes 0-7 -> (m+l, klo), 8-15 -> (m+8+l, klo),
    //                 16-23 -> (m+l, khi), 24-31 -> (m+8+l, khi)
    const int a_row = wm * 64 + (lane & 7) + ((lane >> 3) & 1) * 8;
    const int a_kof = ((lane >> 4) & 1) * 8;
    const uint32_t a_base_off = (uint32_t)(a_row * 128 + a_kof * 2);
    // B (two 8x16 n-tiles): lanes 0-7 -> (n+l, klo), 8-15 -> (n+l, khi),
    //                       16-23 -> (n+8+l, klo), 24-31 -> (n+8+l, khi)
    const int b_row = wn * 32 + (lane & 7) + ((lane >> 4) & 1) * 8;
    const int b_kof = ((lane >> 3) & 1) * 8;
    const uint32_t b_base_off = (uint32_t)(b_row * 128 + b_kof * 2);

    float acc[4][4][4];
#pragma unroll
    for (int mt = 0; mt < 4; ++mt)
#pragma unroll
        for (int nt = 0; nt < 4; ++nt)
#pragma unroll
            for (int i = 0; i < 4; ++i) acc[mt][nt][i] = 0.f;

    const uint32_t Abase[3] = {QHI, QHI, QLO};
    const uint32_t Bbase[3] = {KHI, KLO, KHI};

#pragma unroll
    for (int t = 0; t < 3; ++t) {
#pragma unroll
        for (int ks = 0; ks < 4; ++ks) {
            uint32_t a[4][4];
#pragma unroll
            for (int mt = 0; mt < 4; ++mt) {
                uint32_t off = a_base_off + (uint32_t)(mt * 2048 + ks * 32);
                off = SW128(off);
                LDMATRIX_X4(a[mt][0], a[mt][1], a[mt][2], a[mt][3], Abase[t] + off);
            }
            uint32_t b[4][2];
#pragma unroll
            for (int np = 0; np < 2; ++np) {
                uint32_t off = b_base_off + (uint32_t)(np * 2048 + ks * 32);
                off = SW128(off);
                uint32_t r0, r1, r2, r3;
                LDMATRIX_X4(r0, r1, r2, r3, Bbase[t] + off);
                b[2 * np][0] = r0;  b[2 * np][1] = r1;
                b[2 * np + 1][0] = r2;  b[2 * np + 1][1] = r3;
            }
#pragma unroll
            for (int mt = 0; mt < 4; ++mt)
#pragma unroll
                for (int nt = 0; nt < 4; ++nt)
                    MMA_16816(acc[mt][nt], a[mt], b[nt]);
        }
    }

    // --- epilogue: d2 = q2 + k2 - 2*qk; out = exp(-0.5*max(d2,0))
    const float* q2p = g_q2 + h * NSEQ + row0;
    const float* k2p = g_k2 + h * NSEQ + col0;
    float* outh = out + (size_t)h * NSEQ * NSEQ;

#pragma unroll
    for (int mt = 0; mt < 4; ++mt) {
        const int rA = wm * 64 + mt * 16 + (lane >> 2);
        const int rB = rA + 8;
        const float q2a = q2p[rA];
        const float q2b = q2p[rB];
        float* orowA = outh + (size_t)(row0 + rA) * NSEQ + col0;
        float* orowB = outh + (size_t)(row0 + rB) * NSEQ + col0;
#pragma unroll
        for (int nt = 0; nt < 4; ++nt) {
            const int c = wn * 32 + nt * 8 + (lane & 3) * 2;
            const float k2a = k2p[c];
            const float k2b = k2p[c + 1];
            const float* v = acc[mt][nt];
            float2 oA, oB;
            oA.x = __expf(-0.5f * fmaxf(fmaf(-2.f, v[0], q2a + k2a), 0.f));
            oA.y = __expf(-0.5f * fmaxf(fmaf(-2.f, v[1], q2a + k2b), 0.f));
            oB.x = __expf(-0.5f * fmaxf(fmaf(-2.f, v[2], q2b + k2a), 0.f));
            oB.y = __expf(-0.5f * fmaxf(fmaf(-2.f, v[3], q2b + k2b), 0.f));
            *reinterpret_cast<float2*>(orowA + c) = oA;
            *reinterpret_cast<float2*>(orowB + c) = oB;
        }
    }
}

// ---------------------------------------------------------------------------
extern "C" void kernel_launch(void* const* d_in, const int* in_sizes, int n_in,
                              void* d_out, int out_size) {
    const float* q = (const float*)d_in[0];
    const float* k = (const float*)d_in[1];
    float* out = (float*)d_out;

    cudaFuncSetAttribute(hept_mma_kernel,
                         cudaFuncAttributeMaxDynamicSharedMemorySize, SM_ALLOC);

    dim3 ngrid((HEADS * NSEQ + 255) / 256, 2, 1);
    hept_norms_kernel<<<ngrid, 256>>>(q, k);

    dim3 mgrid(NSEQ / TILE, NSEQ / TILE, HEADS);
    hept_mma_kernel<<<mgrid, 256, SM_ALLOC>>>(q, k, out);
}